// round 9
// baseline (speedup 1.0000x reference)
#include <cuda_runtime.h>

#define NB 16
#define CH 256
#define KS 6
#define MS 22
#define HO 17
#define OUT_PER_N (HO*HO)          // 289
#define TOT_OUT (NB*OUT_PER_N)     // 4624
#define CPB 8                      // channels per block
#define NCHUNK (CH/CPB)            // 32
#define RS 23                      // smem row stride (odd)
#define CSTR 519                   // channel-tile stride; 519 ≡ 23*17 (mod 32)
                                   //  -> lane l bank = 23*l mod 32: conflict-free
#define NTILE 16                   // 2 n-subs * 8 channels
#define TPB 272                    // 17 oy * 8 cl * 2 nsub
#define OXW 9                      // ox-half width (half 1 uses 8)
#define XCOLS 14
#define SCR 153                    // HO*OXW scratch stride per tile
#define IDX4 (TOT_OUT/4)           // 1156 float4 columns

// partials: [chunk][idx], 16B-aligned
__device__ float4 g_p4[NCHUNK * IDX4];
__device__ float4 g_mean4[IDX4];

__device__ __forceinline__ float fsqrt_fast(float a) {
    float r; asm("sqrt.approx.f32 %0, %1;" : "=f"(r) : "f"(a)); return r;
}

// ---------------------------------------------------------------------------
// Kernel 1: per-(chunk, n-pair, ox-half) sliding correlation.
// thread = (oy, cl, nsub): 9 (or 8) sliding outputs, 324 FMA, ~45 regs.
// ---------------------------------------------------------------------------
__global__ __launch_bounds__(TPB, 3) void corr_kernel(
    const float* __restrict__ z, const float* __restrict__ x,
    const float* __restrict__ w)
{
    __shared__ float xs[NTILE * CSTR];        // 8304 floats; reused as scratch
    __shared__ float zs[NTILE * KS * KS];     // 576

    const int chunk = blockIdx.x;
    const int n0    = blockIdx.y * 2;
    const int half  = blockIdx.z;
    const int ox0   = half * OXW;             // 0 or 9
    const int t     = threadIdx.x;

    // --- x load: 16 channel-tiles (2 n x 8 ch), float4 + fused sqrt ---
    for (int e4 = t; e4 < NTILE * 121; e4 += TPB) {
        unsigned tl   = (unsigned)e4 / 121u;          // tile 0..15
        unsigned rem4 = (unsigned)e4 - tl * 121u;
        const float4* src = (const float4*)(
            x + ((size_t)(n0 + (tl >> 3)) * CH + chunk * CPB + (tl & 7)) * (MS * MS));
        float4 v = src[rem4];
        unsigned r0   = (2u * rem4) / 11u;            // (4*rem4)/22
        unsigned c0   = 4u * rem4 - 22u * r0;         // even, 0..20
        unsigned base = tl * CSTR + r0 * RS + c0;
        unsigned p    = (c0 == 20u) ? 1u : 0u;        // wrap shifts exactly +1
        xs[base + 0]     = fsqrt_fast(v.x);
        xs[base + 1]     = fsqrt_fast(v.y);
        xs[base + 2 + p] = fsqrt_fast(v.z);
        xs[base + 3 + p] = fsqrt_fast(v.w);
    }
    // --- z load ---
    for (int e = t; e < NTILE * KS * KS; e += TPB) {
        unsigned tl = (unsigned)e / 36u;
        unsigned k  = (unsigned)e - tl * 36u;
        int c = chunk * CPB + (tl & 7);
        zs[e] = fsqrt_fast(z[((size_t)(n0 + (tl >> 3)) * CH + c) * 36 + k]) * w[c];
    }
    __syncthreads();

    // --- compute: thread = (oy, cl, nsub); 9 sliding outputs ---
    const int r    = t % 136;
    const int nsub = t / 136;
    const int oy   = r % HO;
    const int cl   = r / HO;
    const int tile = nsub * CPB + cl;
    const float* xb = &xs[tile * CSTR + ox0];
    const float* zb = &zs[tile * KS * KS];

    float acc[OXW];
#pragma unroll
    for (int i = 0; i < OXW; i++) acc[i] = 0.f;

#pragma unroll
    for (int k1 = 0; k1 < KS; k1++) {
        float xr[XCOLS];
        // NOTE: for half==1 j==13 hits the (never-written) pad word of the
        // last column; it only feeds acc[8], which half==1 discards below.
#pragma unroll
        for (int j = 0; j < XCOLS; j++) xr[j] = xb[(oy + k1) * RS + j];
#pragma unroll
        for (int k2 = 0; k2 < KS; k2++) {
            float zv = zb[k1 * KS + k2];
#pragma unroll
            for (int i = 0; i < OXW; i++)
                acc[i] = fmaf(xr[i + k2], zv, acc[i]);
        }
    }

    // --- reduce 8 channel lanes per nsub (fixed order -> deterministic) ---
    __syncthreads();
    float* scratch = xs;                      // 16 * 153 = 2448 floats
#pragma unroll
    for (int i = 0; i < OXW; i++)
        scratch[tile * SCR + oy * OXW + i] = acc[i];
    __syncthreads();

    float* gp = (float*)g_p4;                 // [chunk][4624]
    for (int q = t; q < 2 * SCR; q += TPB) {
        int ns  = (q >= SCR) ? 1 : 0;
        int idx = q - ns * SCR;
        int oyo = idx / OXW;
        int i   = idx - oyo * OXW;
        if (half == 1 && i == OXW - 1) continue;     // half 1: only 8 outputs
        float s = 0.f;
#pragma unroll
        for (int c2 = 0; c2 < CPB; c2++)
            s += scratch[(ns * CPB + c2) * SCR + idx];
        gp[chunk * TOT_OUT + (n0 + ns) * OUT_PER_N + oyo * HO + ox0 + i] = s;
    }
}

// ---------------------------------------------------------------------------
// Kernel 2: chunk reduce (32 chunks) spread over 10 blocks, 4 indep chains.
// ---------------------------------------------------------------------------
#define CRB 128
__global__ __launch_bounds__(CRB) void chunk_reduce()
{
    int idx4 = blockIdx.x * CRB + threadIdx.x;
    if (idx4 >= IDX4) return;

    float4 a0 = make_float4(0.f,0.f,0.f,0.f), a1 = a0, a2 = a0, a3 = a0;
#pragma unroll
    for (int ch = 0; ch < NCHUNK; ch += 4) {
        float4 p0 = g_p4[(ch + 0) * IDX4 + idx4];
        float4 p1 = g_p4[(ch + 1) * IDX4 + idx4];
        float4 p2 = g_p4[(ch + 2) * IDX4 + idx4];
        float4 p3 = g_p4[(ch + 3) * IDX4 + idx4];
        a0.x += p0.x; a0.y += p0.y; a0.z += p0.z; a0.w += p0.w;
        a1.x += p1.x; a1.y += p1.y; a1.z += p1.z; a1.w += p1.w;
        a2.x += p2.x; a2.y += p2.y; a2.z += p2.z; a2.w += p2.w;
        a3.x += p3.x; a3.y += p3.y; a3.z += p3.z; a3.w += p3.w;
    }
    float4 r;
    r.x = ((a0.x + a1.x) + (a2.x + a3.x)) * (1.f/36.f);
    r.y = ((a0.y + a1.y) + (a2.y + a3.y)) * (1.f/36.f);
    r.z = ((a0.z + a1.z) + (a2.z + a3.z)) * (1.f/36.f);
    r.w = ((a0.w + a1.w) + (a2.w + a3.w)) * (1.f/36.f);
    g_mean4[idx4] = r;
}

// ---------------------------------------------------------------------------
// Kernel 3: single-block BatchNorm over 4624 values (reads only 18.5 KB).
// ---------------------------------------------------------------------------
#define BNT 512
#define NG 3
__global__ __launch_bounds__(BNT) void finalize(
    float* __restrict__ out,
    const float* __restrict__ bw, const float* __restrict__ bb)
{
    __shared__ float sred[BNT];
    __shared__ float s_mu, s_scale;
    const int t = threadIdx.x;
    const bool own3 = (t < IDX4 - 2 * BNT);   // 1156 - 1024 = 132

    float4 v[NG];
    float lsum = 0.f;
#pragma unroll
    for (int g = 0; g < NG; g++) {
        float4 a = make_float4(0.f,0.f,0.f,0.f);
        if (g < 2 || own3) a = g_mean4[t + g * BNT];
        v[g] = a;
        lsum += (a.x + a.y) + (a.z + a.w);
    }

    sred[t] = lsum; __syncthreads();
    for (int sz = BNT / 2; sz > 0; sz >>= 1) { if (t < sz) sred[t] += sred[t + sz]; __syncthreads(); }
    if (t == 0) s_mu = sred[0] / (float)TOT_OUT;
    __syncthreads();
    const float mu = s_mu;

    float lss = 0.f;
#pragma unroll
    for (int g = 0; g < NG; g++) {
        if (g == 2 && !own3) break;
        float dx = v[g].x - mu, dy = v[g].y - mu, dz = v[g].z - mu, dw = v[g].w - mu;
        lss += (dx*dx + dy*dy) + (dz*dz + dw*dw);
    }
    sred[t] = lss; __syncthreads();
    for (int sz = BNT / 2; sz > 0; sz >>= 1) { if (t < sz) sred[t] += sred[t + sz]; __syncthreads(); }
    if (t == 0) s_scale = rsqrtf(sred[0] / (float)TOT_OUT + 1e-5f) * bw[0];
    __syncthreads();
    const float scale = s_scale;
    const float bias  = bb[0];

#pragma unroll
    for (int g = 0; g < NG; g++) {
        if (g == 2 && !own3) break;
        float4 o;
        o.x = (v[g].x - mu) * scale + bias;
        o.y = (v[g].y - mu) * scale + bias;
        o.z = (v[g].z - mu) * scale + bias;
        o.w = (v[g].w - mu) * scale + bias;
        ((float4*)out)[t + g * BNT] = o;
    }
}

extern "C" void kernel_launch(void* const* d_in, const int* in_sizes, int n_in,
                              void* d_out, int out_size)
{
    const float* z  = (const float*)d_in[0];
    const float* x  = (const float*)d_in[1];
    const float* w  = (const float*)d_in[2];
    const float* bw = (const float*)d_in[3];
    const float* bb = (const float*)d_in[4];

    int first_one = -1;
    for (int i = 0; i < n_in; i++) {
        if (in_sizes[i] == NB * CH * KS * KS)      z = (const float*)d_in[i];
        else if (in_sizes[i] == NB * CH * MS * MS) x = (const float*)d_in[i];
        else if (in_sizes[i] == CH)                w = (const float*)d_in[i];
        else if (in_sizes[i] == 1) {
            if (first_one < 0) { bw = (const float*)d_in[i]; first_one = i; }
            else                 bb = (const float*)d_in[i];
        }
    }

    dim3 grid(NCHUNK, NB / 2, 2);                // 32 x 8 x 2 = 512 blocks
    corr_kernel<<<grid, TPB>>>(z, x, w);
    chunk_reduce<<<(IDX4 + CRB - 1) / CRB, CRB>>>();   // 10 blocks
    finalize<<<1, BNT>>>((float*)d_out, bw, bb);
}

// round 10
// speedup vs baseline: 1.2391x; 1.2391x over previous
#include <cuda_runtime.h>

#define NB 16
#define CH 256
#define KS 6
#define MS 22
#define HO 17
#define OUT_PER_N (HO*HO)          // 289
#define TOT_OUT (NB*OUT_PER_N)     // 4624
#define CPB 16                     // channels per block
#define NCHUNK (CH/CPB)            // 16
#define RS 23                      // smem row stride
#define CSTR 507                   // channel tile stride (odd -> reduced conflicts)
#define ZSTR 37                    // z tile stride (odd)
#define TPB 288                    // 16 cl * 9 pairs * 2 halves
#define OXW 9
#define XCOLS 14
#define IDX4 (TOT_OUT/4)           // 1156 float4 columns

// partials: [chunk][idx], 16B-aligned
__device__ float4 g_p4[NCHUNK * IDX4];
__device__ float4 g_mean4[IDX4];

__device__ __forceinline__ float fsqrt_fast(float a) {
    float r; asm("sqrt.approx.f32 %0, %1;" : "=f"(r) : "f"(a)); return r;
}

// ---------------------------------------------------------------------------
// Kernel 1: per-(chunk, n) sliding correlation.
// thread = (channel, oy-pair, ox-half): 2 output rows x 9 cols.
// 648 FMA / 98 x-LDS per thread; 36 z taps in registers; x loaded once.
// ---------------------------------------------------------------------------
__global__ __launch_bounds__(TPB, 2) void corr_kernel(
    const float* __restrict__ z, const float* __restrict__ x,
    const float* __restrict__ w)
{
    __shared__ float xs[CPB * CSTR];      // 8112 floats; reused as reduce scratch
    __shared__ float zs[CPB * ZSTR];      // 592

    const int chunk = blockIdx.x;
    const int n     = blockIdx.y;
    const int t     = threadIdx.x;

    // --- x load: float4 + fused sqrt; 1936 float4 over 288 threads ---
    const float4* xg4 = (const float4*)(x + (size_t)(n * CH + chunk * CPB) * (MS * MS));
    for (int e4 = t; e4 < CPB * 121; e4 += TPB) {
        float4 v = xg4[e4];
        unsigned cl   = (unsigned)e4 / 121u;
        unsigned rem4 = (unsigned)e4 - cl * 121u;
        unsigned r0   = (2u * rem4) / 11u;            // (4*rem4)/22
        unsigned c0   = 4u * rem4 - 22u * r0;         // even, 0..20
        unsigned base = cl * CSTR + r0 * RS + c0;
        unsigned p    = (c0 == 20u) ? 1u : 0u;        // wrap shifts exactly +1
        xs[base + 0]     = fsqrt_fast(v.x);
        xs[base + 1]     = fsqrt_fast(v.y);
        xs[base + 2 + p] = fsqrt_fast(v.z);
        xs[base + 3 + p] = fsqrt_fast(v.w);
    }
    // --- z load ---
    const float* zg = z + (size_t)(n * CH + chunk * CPB) * (KS * KS);
    for (int e = t; e < CPB * KS * KS; e += TPB) {
        unsigned cl = (unsigned)e / 36u;
        unsigned k  = (unsigned)e - cl * 36u;
        zs[cl * ZSTR + k] = fsqrt_fast(zg[e]) * w[chunk * CPB + cl];
    }
    __syncthreads();

    // --- compute: thread = (cl, pair, half); rows oy0, oy0+1; cols ox0..+8 ---
    const int cl   = t & 15;
    const int ph   = t >> 4;              // 0..17
    const int pair = ph % 9;
    const int half = ph / 9;
    const int oy0  = pair * 2;            // 0..16 (pair 8: single row)
    const int ox0  = half * OXW;          // 0 or 9
    const float* xb = &xs[cl * CSTR + ox0];

    float zr[KS * KS];
#pragma unroll
    for (int i = 0; i < KS * KS; i++) zr[i] = zs[cl * ZSTR + i];

    float a0[OXW], a1[OXW];
#pragma unroll
    for (int i = 0; i < OXW; i++) { a0[i] = 0.f; a1[i] = 0.f; }

#pragma unroll
    for (int r = 0; r < 7; r++) {
        int row = oy0 + r;
        if (row > MS - 1) row = MS - 1;   // pair 8, r==6: dummy (feeds a1 only)
        float xr[XCOLS];
        // half==1, j==13 reads the pad slot (col 22): feeds only acc[8],
        // which half 1 discards below.
#pragma unroll
        for (int j = 0; j < XCOLS; j++) xr[j] = xb[row * RS + j];
        if (r < 6) {                      // out-row 0, tap k1=r
#pragma unroll
            for (int k2 = 0; k2 < KS; k2++) {
                float zv = zr[r * KS + k2];
#pragma unroll
                for (int i = 0; i < OXW; i++)
                    a0[i] = fmaf(xr[i + k2], zv, a0[i]);
            }
        }
        if (r >= 1) {                     // out-row 1, tap k1=r-1
#pragma unroll
            for (int k2 = 0; k2 < KS; k2++) {
                float zv = zr[(r - 1) * KS + k2];
#pragma unroll
                for (int i = 0; i < OXW; i++)
                    a1[i] = fmaf(xr[i + k2], zv, a1[i]);
            }
        }
    }

    // --- block reduce over 16 channel lanes (fixed order -> deterministic) ---
    __syncthreads();
    float* scratch = xs;                  // 16 * 289 = 4624 floats
    const int nox = (half == 0) ? OXW : (OXW - 1);   // 9 or 8 valid cols
#pragma unroll
    for (int i = 0; i < OXW; i++) {
        if (i < nox)
            scratch[cl * OUT_PER_N + oy0 * HO + ox0 + i] = a0[i];
    }
    if (pair < 8) {
#pragma unroll
        for (int i = 0; i < OXW; i++) {
            if (i < nox)
                scratch[cl * OUT_PER_N + (oy0 + 1) * HO + ox0 + i] = a1[i];
        }
    }
    __syncthreads();

    float* gp = (float*)g_p4;             // [chunk][4624]
    for (int idx = t; idx < OUT_PER_N; idx += TPB) {
        float s = 0.f;
#pragma unroll
        for (int c2 = 0; c2 < CPB; c2++) s += scratch[c2 * OUT_PER_N + idx];
        gp[chunk * TOT_OUT + n * OUT_PER_N + idx] = s;
    }
}

// ---------------------------------------------------------------------------
// Kernel 2: chunk reduce (16 chunks) spread over 10 blocks, 4 indep chains.
// ---------------------------------------------------------------------------
#define CRB 128
__global__ __launch_bounds__(CRB) void chunk_reduce()
{
    int idx4 = blockIdx.x * CRB + threadIdx.x;
    if (idx4 >= IDX4) return;

    float4 a0 = make_float4(0.f,0.f,0.f,0.f), a1 = a0, a2 = a0, a3 = a0;
#pragma unroll
    for (int ch = 0; ch < NCHUNK; ch += 4) {
        float4 p0 = g_p4[(ch + 0) * IDX4 + idx4];
        float4 p1 = g_p4[(ch + 1) * IDX4 + idx4];
        float4 p2 = g_p4[(ch + 2) * IDX4 + idx4];
        float4 p3 = g_p4[(ch + 3) * IDX4 + idx4];
        a0.x += p0.x; a0.y += p0.y; a0.z += p0.z; a0.w += p0.w;
        a1.x += p1.x; a1.y += p1.y; a1.z += p1.z; a1.w += p1.w;
        a2.x += p2.x; a2.y += p2.y; a2.z += p2.z; a2.w += p2.w;
        a3.x += p3.x; a3.y += p3.y; a3.z += p3.z; a3.w += p3.w;
    }
    float4 r;
    r.x = ((a0.x + a1.x) + (a2.x + a3.x)) * (1.f/36.f);
    r.y = ((a0.y + a1.y) + (a2.y + a3.y)) * (1.f/36.f);
    r.z = ((a0.z + a1.z) + (a2.z + a3.z)) * (1.f/36.f);
    r.w = ((a0.w + a1.w) + (a2.w + a3.w)) * (1.f/36.f);
    g_mean4[idx4] = r;
}

// ---------------------------------------------------------------------------
// Kernel 3: single-block BatchNorm over 4624 values (reads only 18.5 KB).
// ---------------------------------------------------------------------------
#define BNT 512
#define NG 3
__global__ __launch_bounds__(BNT) void finalize(
    float* __restrict__ out,
    const float* __restrict__ bw, const float* __restrict__ bb)
{
    __shared__ float sred[BNT];
    __shared__ float s_mu, s_scale;
    const int t = threadIdx.x;
    const bool own3 = (t < IDX4 - 2 * BNT);   // 1156 - 1024 = 132

    float4 v[NG];
    float lsum = 0.f;
#pragma unroll
    for (int g = 0; g < NG; g++) {
        float4 a = make_float4(0.f,0.f,0.f,0.f);
        if (g < 2 || own3) a = g_mean4[t + g * BNT];
        v[g] = a;
        lsum += (a.x + a.y) + (a.z + a.w);
    }

    sred[t] = lsum; __syncthreads();
    for (int sz = BNT / 2; sz > 0; sz >>= 1) { if (t < sz) sred[t] += sred[t + sz]; __syncthreads(); }
    if (t == 0) s_mu = sred[0] / (float)TOT_OUT;
    __syncthreads();
    const float mu = s_mu;

    float lss = 0.f;
#pragma unroll
    for (int g = 0; g < NG; g++) {
        if (g == 2 && !own3) break;
        float dx = v[g].x - mu, dy = v[g].y - mu, dz = v[g].z - mu, dw = v[g].w - mu;
        lss += (dx*dx + dy*dy) + (dz*dz + dw*dw);
    }
    sred[t] = lss; __syncthreads();
    for (int sz = BNT / 2; sz > 0; sz >>= 1) { if (t < sz) sred[t] += sred[t + sz]; __syncthreads(); }
    if (t == 0) s_scale = rsqrtf(sred[0] / (float)TOT_OUT + 1e-5f) * bw[0];
    __syncthreads();
    const float scale = s_scale;
    const float bias  = bb[0];

#pragma unroll
    for (int g = 0; g < NG; g++) {
        if (g == 2 && !own3) break;
        float4 o;
        o.x = (v[g].x - mu) * scale + bias;
        o.y = (v[g].y - mu) * scale + bias;
        o.z = (v[g].z - mu) * scale + bias;
        o.w = (v[g].w - mu) * scale + bias;
        ((float4*)out)[t + g * BNT] = o;
    }
}

extern "C" void kernel_launch(void* const* d_in, const int* in_sizes, int n_in,
                              void* d_out, int out_size)
{
    const float* z  = (const float*)d_in[0];
    const float* x  = (const float*)d_in[1];
    const float* w  = (const float*)d_in[2];
    const float* bw = (const float*)d_in[3];
    const float* bb = (const float*)d_in[4];

    int first_one = -1;
    for (int i = 0; i < n_in; i++) {
        if (in_sizes[i] == NB * CH * KS * KS)      z = (const float*)d_in[i];
        else if (in_sizes[i] == NB * CH * MS * MS) x = (const float*)d_in[i];
        else if (in_sizes[i] == CH)                w = (const float*)d_in[i];
        else if (in_sizes[i] == 1) {
            if (first_one < 0) { bw = (const float*)d_in[i]; first_one = i; }
            else                 bb = (const float*)d_in[i];
        }
    }

    dim3 grid(NCHUNK, NB);                       // 16 x 16 = 256 blocks
    corr_kernel<<<grid, TPB>>>(z, x, w);
    chunk_reduce<<<(IDX4 + CRB - 1) / CRB, CRB>>>();   // 10 blocks
    finalize<<<1, BNT>>>((float*)d_out, bw, bb);
}

// round 11
// speedup vs baseline: 1.3864x; 1.1189x over previous
#include <cuda_runtime.h>

#define NB 16
#define CH 256
#define KS 6
#define MS 22
#define HO 17
#define OUT_PER_N (HO*HO)          // 289
#define TOT_OUT (NB*OUT_PER_N)     // 4624
#define CPB 16                     // channels per block
#define NCHUNK (CH/CPB)            // 16
#define RS 23                      // smem row stride
#define CSTR 507                   // channel tile stride
#define ZSTR 37                    // z tile stride
#define TPB 288                    // 16 cl * 9 pairs * 2 halves
#define OXW 9
#define XCOLS 14
#define IDX4 (TOT_OUT/4)           // 1156 float4 columns
#define NL 7                       // ceil(1936/288) front-batched loads/thread

// partials: [chunk][idx], 16B-aligned
__device__ float4 g_p4[NCHUNK * IDX4];
__device__ float4 g_mean4[IDX4];
__device__ int    g_count = 0;     // returns to 0 every launch

__device__ __forceinline__ float fsqrt_fast(float a) {
    float r; asm("sqrt.approx.f32 %0, %1;" : "=f"(r) : "f"(a)); return r;
}
__device__ __forceinline__ float4 ldcg4(const float4* p) {
    float4 v;
    asm volatile("ld.global.cg.v4.f32 {%0,%1,%2,%3}, [%4];"
                 : "=f"(v.x), "=f"(v.y), "=f"(v.z), "=f"(v.w) : "l"(p));
    return v;
}

// ---------------------------------------------------------------------------
// Kernel 1: per-(chunk, n) sliding correlation.
// Load phase front-batches 7 LDG.128 per thread (MLP=7) before any STS.
// Compute: thread = (channel, oy-pair, ox-half): 2 rows x 9 cols, z in regs.
// ---------------------------------------------------------------------------
__global__ __launch_bounds__(TPB, 2) void corr_kernel(
    const float* __restrict__ z, const float* __restrict__ x,
    const float* __restrict__ w)
{
    __shared__ float xs[CPB * CSTR];      // 8112 floats; reused as reduce scratch
    __shared__ float zs[CPB * ZSTR];      // 592

    const int chunk = blockIdx.x;
    const int n     = blockIdx.y;
    const int t     = threadIdx.x;

    // --- phase A: front-batched gmem loads (7 independent LDG.128) ---
    const float4* xg4 = (const float4*)(x + (size_t)(n * CH + chunk * CPB) * (MS * MS));
    float4 v[NL];
#pragma unroll
    for (int i = 0; i < NL; i++) {
        int e4 = t + i * TPB;
        if (e4 < CPB * 121) v[i] = xg4[e4];
    }
    // z: 2 loads/thread, also front-batched
    const float* zg = z + (size_t)(n * CH + chunk * CPB) * (KS * KS);
    float zv0 = 0.f, zv1 = 0.f;
    {
        int e0 = t, e1 = t + TPB;
        if (e0 < CPB * KS * KS) zv0 = zg[e0];
        if (e1 < CPB * KS * KS) zv1 = zg[e1];
    }

    // --- phase B: sqrt + smem stores ---
#pragma unroll
    for (int i = 0; i < NL; i++) {
        int e4 = t + i * TPB;
        if (e4 < CPB * 121) {
            unsigned cl   = (unsigned)e4 / 121u;
            unsigned rem4 = (unsigned)e4 - cl * 121u;
            unsigned r0   = (2u * rem4) / 11u;        // (4*rem4)/22
            unsigned c0   = 4u * rem4 - 22u * r0;     // even, 0..20
            unsigned base = cl * CSTR + r0 * RS + c0;
            unsigned p    = (c0 == 20u) ? 1u : 0u;    // wrap shifts exactly +1
            xs[base + 0]     = fsqrt_fast(v[i].x);
            xs[base + 1]     = fsqrt_fast(v[i].y);
            xs[base + 2 + p] = fsqrt_fast(v[i].z);
            xs[base + 3 + p] = fsqrt_fast(v[i].w);
        }
    }
    {
        int e0 = t, e1 = t + TPB;
        if (e0 < CPB * KS * KS) {
            unsigned cl = (unsigned)e0 / 36u, k = (unsigned)e0 - cl * 36u;
            zs[cl * ZSTR + k] = fsqrt_fast(zv0) * w[chunk * CPB + cl];
        }
        if (e1 < CPB * KS * KS) {
            unsigned cl = (unsigned)e1 / 36u, k = (unsigned)e1 - cl * 36u;
            zs[cl * ZSTR + k] = fsqrt_fast(zv1) * w[chunk * CPB + cl];
        }
    }
    __syncthreads();

    // --- compute: thread = (cl, pair, half) ---
    const int cl   = t & 15;
    const int ph   = t >> 4;              // 0..17
    const int pair = ph % 9;
    const int half = ph / 9;
    const int oy0  = pair * 2;            // 0..16 (pair 8: single row)
    const int ox0  = half * OXW;          // 0 or 9
    const float* xb = &xs[cl * CSTR + ox0];

    float zr[KS * KS];
#pragma unroll
    for (int i = 0; i < KS * KS; i++) zr[i] = zs[cl * ZSTR + i];

    float a0[OXW], a1[OXW];
#pragma unroll
    for (int i = 0; i < OXW; i++) { a0[i] = 0.f; a1[i] = 0.f; }

#pragma unroll
    for (int r = 0; r < 7; r++) {
        int row = oy0 + r;
        if (row > MS - 1) row = MS - 1;   // pair 8, r==6: dummy (feeds a1 only)
        float xr[XCOLS];
        // half==1, j==13 reads the pad slot: feeds only acc[8], discarded below.
#pragma unroll
        for (int j = 0; j < XCOLS; j++) xr[j] = xb[row * RS + j];
        if (r < 6) {
#pragma unroll
            for (int k2 = 0; k2 < KS; k2++) {
                float zv = zr[r * KS + k2];
#pragma unroll
                for (int i = 0; i < OXW; i++)
                    a0[i] = fmaf(xr[i + k2], zv, a0[i]);
            }
        }
        if (r >= 1) {
#pragma unroll
            for (int k2 = 0; k2 < KS; k2++) {
                float zv = zr[(r - 1) * KS + k2];
#pragma unroll
                for (int i = 0; i < OXW; i++)
                    a1[i] = fmaf(xr[i + k2], zv, a1[i]);
            }
        }
    }

    // --- block reduce over 16 channel lanes (fixed order -> deterministic) ---
    __syncthreads();
    float* scratch = xs;                  // 16 * 289 = 4624 floats
    const int nox = (half == 0) ? OXW : (OXW - 1);
#pragma unroll
    for (int i = 0; i < OXW; i++)
        if (i < nox) scratch[cl * OUT_PER_N + oy0 * HO + ox0 + i] = a0[i];
    if (pair < 8) {
#pragma unroll
        for (int i = 0; i < OXW; i++)
            if (i < nox) scratch[cl * OUT_PER_N + (oy0 + 1) * HO + ox0 + i] = a1[i];
    }
    __syncthreads();

    float* gp = (float*)g_p4;             // [chunk][4624]
    for (int idx = t; idx < OUT_PER_N; idx += TPB) {
        float s = 0.f;
#pragma unroll
        for (int c2 = 0; c2 < CPB; c2++) s += scratch[c2 * OUT_PER_N + idx];
        gp[chunk * TOT_OUT + n * OUT_PER_N + idx] = s;
    }
}

// ---------------------------------------------------------------------------
// Kernel 2 (fused): 10-block chunk reduce, then last block does BatchNorm.
// ---------------------------------------------------------------------------
#define CRB 128
#define CRG ((IDX4 + CRB - 1) / CRB)      // 10 blocks
#define VPT 10                            // 128*10 >= 1156 float4 columns
__global__ __launch_bounds__(CRB) void reduce_bn(
    float* __restrict__ out,
    const float* __restrict__ bw, const float* __restrict__ bb)
{
    const int t = threadIdx.x;
    const int idx4 = blockIdx.x * CRB + t;

    if (idx4 < IDX4) {
        float4 a0 = make_float4(0.f,0.f,0.f,0.f), a1 = a0, a2 = a0, a3 = a0;
#pragma unroll
        for (int ch = 0; ch < NCHUNK; ch += 4) {
            float4 p0 = g_p4[(ch + 0) * IDX4 + idx4];
            float4 p1 = g_p4[(ch + 1) * IDX4 + idx4];
            float4 p2 = g_p4[(ch + 2) * IDX4 + idx4];
            float4 p3 = g_p4[(ch + 3) * IDX4 + idx4];
            a0.x += p0.x; a0.y += p0.y; a0.z += p0.z; a0.w += p0.w;
            a1.x += p1.x; a1.y += p1.y; a1.z += p1.z; a1.w += p1.w;
            a2.x += p2.x; a2.y += p2.y; a2.z += p2.z; a2.w += p2.w;
            a3.x += p3.x; a3.y += p3.y; a3.z += p3.z; a3.w += p3.w;
        }
        float4 r;
        r.x = ((a0.x + a1.x) + (a2.x + a3.x)) * (1.f/36.f);
        r.y = ((a0.y + a1.y) + (a2.y + a3.y)) * (1.f/36.f);
        r.z = ((a0.z + a1.z) + (a2.z + a3.z)) * (1.f/36.f);
        r.w = ((a0.w + a1.w) + (a2.w + a3.w)) * (1.f/36.f);
        g_mean4[idx4] = r;
    }

    // --- last-block-done ticket ---
    __threadfence();
    __syncthreads();
    __shared__ bool amLast;
    if (t == 0) amLast = (atomicAdd(&g_count, 1) == CRG - 1);
    __syncthreads();
    if (!amLast) return;

    // --- BatchNorm over 4624 values (18.5 KB, front-batched L2 reads) ---
    __shared__ float sred[CRB];
    __shared__ float s_mu, s_scale;

    float4 v[VPT];
#pragma unroll
    for (int g = 0; g < VPT; g++) {
        int i4 = t + g * CRB;
        v[g] = (i4 < IDX4) ? ldcg4(&g_mean4[i4]) : make_float4(0.f,0.f,0.f,0.f);
    }
    float lsum = 0.f;
#pragma unroll
    for (int g = 0; g < VPT; g++)
        lsum += (v[g].x + v[g].y) + (v[g].z + v[g].w);

    sred[t] = lsum; __syncthreads();
    for (int sz = CRB / 2; sz > 0; sz >>= 1) { if (t < sz) sred[t] += sred[t + sz]; __syncthreads(); }
    if (t == 0) s_mu = sred[0] / (float)TOT_OUT;
    __syncthreads();
    const float mu = s_mu;

    float lss = 0.f;
#pragma unroll
    for (int g = 0; g < VPT; g++) {
        int i4 = t + g * CRB;
        if (i4 < IDX4) {
            float dx = v[g].x - mu, dy = v[g].y - mu, dz = v[g].z - mu, dw = v[g].w - mu;
            lss += (dx*dx + dy*dy) + (dz*dz + dw*dw);
        }
    }
    sred[t] = lss; __syncthreads();
    for (int sz = CRB / 2; sz > 0; sz >>= 1) { if (t < sz) sred[t] += sred[t + sz]; __syncthreads(); }
    if (t == 0) s_scale = rsqrtf(sred[0] / (float)TOT_OUT + 1e-5f) * bw[0];
    __syncthreads();
    const float scale = s_scale;
    const float bias  = bb[0];

#pragma unroll
    for (int g = 0; g < VPT; g++) {
        int i4 = t + g * CRB;
        if (i4 < IDX4) {
            float4 o;
            o.x = (v[g].x - mu) * scale + bias;
            o.y = (v[g].y - mu) * scale + bias;
            o.z = (v[g].z - mu) * scale + bias;
            o.w = (v[g].w - mu) * scale + bias;
            ((float4*)out)[i4] = o;
        }
    }

    if (t == 0) g_count = 0;              // reset for next graph replay
}

extern "C" void kernel_launch(void* const* d_in, const int* in_sizes, int n_in,
                              void* d_out, int out_size)
{
    const float* z  = (const float*)d_in[0];
    const float* x  = (const float*)d_in[1];
    const float* w  = (const float*)d_in[2];
    const float* bw = (const float*)d_in[3];
    const float* bb = (const float*)d_in[4];

    int first_one = -1;
    for (int i = 0; i < n_in; i++) {
        if (in_sizes[i] == NB * CH * KS * KS)      z = (const float*)d_in[i];
        else if (in_sizes[i] == NB * CH * MS * MS) x = (const float*)d_in[i];
        else if (in_sizes[i] == CH)                w = (const float*)d_in[i];
        else if (in_sizes[i] == 1) {
            if (first_one < 0) { bw = (const float*)d_in[i]; first_one = i; }
            else                 bb = (const float*)d_in[i];
        }
    }

    dim3 grid(NCHUNK, NB);                       // 16 x 16 = 256 blocks
    corr_kernel<<<grid, TPB>>>(z, x, w);
    reduce_bn<<<CRG, CRB>>>((float*)d_out, bw, bb);
}